// round 10
// baseline (speedup 1.0000x reference)
#include <cuda_runtime.h>

// Two Euler steps of a Gaussian-RBF point flow — single persistent kernel,
// tuned for warp occupancy (8 warps/SMSP) after LDS was de-bottlenecked.
//   Phase A: dp1 PARTIALS for all 16384 land rows. 512 CTAs x 256 thr:
//            CTA = 64 rows x half the j-range (512 pairs, 64 steps/warp).
//   Grid barrier (monotonic counter; 512 CTAs resident at 4 CTAs/SM).
//   Phase B: dp2. CTA = 64 target rows x quarter j-range (256 pairs,
//            32 steps/warp). Staging rebuilds the shape1-packed tables from
//            dp1 partials on the fly. 4-way parity-flag combine -> output.
// Row-block x2: each lane owns 2 rows; FFMA2 packs PAIRS of source points;
// one 40B table load serves 2 rows x 2 j.
// Inner exponent: safe combined form arg = u*x + v*y + a + cri <= 0.

#define NSRC  2048
#define NTGT  2048
#define NLAND 4096
#define NB    4
#define NCTA  512
#define TAUF  0.5f
#define LOG2E 1.4426950408889634f

typedef unsigned long long ull;

// Cross-phase scratch (device globals; no allocation).
__device__ float2 g_p1[2][NB * NLAND];   // dp1 partials per j-half
__device__ float2 g_p2[4][NB * NTGT];    // dp2 partials per j-quarter
__device__ ull      g_ctr;               // grid barrier, monotonic across calls
__device__ unsigned g_flag[128];         // per-group arrival count, monotonic

__device__ __forceinline__ float ex2f(float x) {
    float y;
    asm("ex2.approx.ftz.f32 %0, %1;" : "=f"(y) : "f"(x));
    return y;
}
__device__ __forceinline__ ull fma2(ull a, ull b, ull c) {
    ull d;
    asm("fma.rn.f32x2 %0, %1, %2, %3;" : "=l"(d) : "l"(a), "l"(b), "l"(c));
    return d;
}
__device__ __forceinline__ ull add2(ull a, ull b) {
    ull d;
    asm("add.rn.f32x2 %0, %1, %2;" : "=l"(d) : "l"(a), "l"(b));
    return d;
}
__device__ __forceinline__ ull pack2(float lo, float hi) {
    ull d;
    asm("mov.b64 %0, {%1, %2};" : "=l"(d) : "f"(lo), "f"(hi));
    return d;
}
__device__ __forceinline__ void unpack2(ull v, float& lo, float& hi) {
    asm("mov.b64 {%0, %1}, %2;" : "=f"(lo), "=f"(hi) : "l"(v));
}

// One row's packed update for a loaded j-pair.
__device__ __forceinline__ void rbf_row(
    ull UVx, ull UVy, ull APa, ull APp, ull PY,
    ull xp, ull yp, ull crip, ull& ax, ull& ay)
{
    ull arg = add2(fma2(UVy, yp, fma2(UVx, xp, APa)), crip);
    float a0, a1;
    unpack2(arg, a0, a1);
    ull wp = pack2(ex2f(a0), ex2f(a1));
    ax = fma2(wp, APp, ax);
    ay = fma2(wp, PY, ay);
}

// ---------------------------------------------------------------------------
__global__ __launch_bounds__(256, 4) void fused_kernel(
    const float2* __restrict__ mom,
    const float2* __restrict__ src,
    const float2* __restrict__ tgt,
    const float*  __restrict__ sig,
    float2*       __restrict__ out)
{
    // Layout: sUV [0,8K) | sAP [8K,16K) | sPY [16K,20K).
    // Reduction buffer (8KB) aliases sUV after a syncthreads.
    __shared__ __align__(16) char SM[20480];
    float4* sUV = (float4*)(SM);
    float4* sAP = (float4*)(SM + 8192);
    float2* sPY = (float2*)(SM + 16384);
    typedef ull RedRow[256];                 // [warp*32+lane]
    RedRow* red = (RedRow*)(SM);             // red[4][256] = 8KB, aliases sUV

    const int tid  = threadIdx.x;
    const int w    = tid >> 5;
    const int lane = tid & 31;
    const int g    = blockIdx.x;

    const float c2 = -LOG2E / sig[0];
    const float m2 = -2.0f * c2;

    // ======================= Phase A: dp1 partials =======================
    {
        const int grp = g >> 1;              // 0..255: 64-row land group
        const int sj  = g & 1;               // j-half
        const int i0  = grp * 64;            // global land row base
        const int b   = i0 >> 12;
        const int li  = i0 & (NLAND - 1);

        const float2* __restrict__ srcb = src + b * NSRC;
        const float2* __restrict__ momb = mom + b * NSRC;

        const int pbase = sj * 512;          // pair range [pbase, pbase+512)
        for (int q = tid; q < 512; q += 256) {
            const int p = pbase + q;
            float2 s0 = srcb[2 * p], s1 = srcb[2 * p + 1];
            float2 q0 = momb[2 * p], q1 = momb[2 * p + 1];
            sUV[q] = make_float4(m2 * s0.x, m2 * s1.x, m2 * s0.y, m2 * s1.y);
            sAP[q] = make_float4(c2 * (s0.x * s0.x + s0.y * s0.y),
                                 c2 * (s1.x * s1.x + s1.y * s1.y), q0.x, q1.x);
            sPY[q] = make_float2(q0.y, q1.y);
        }
        __syncthreads();

        const int r0 = li + lane, r1 = r0 + 32;     // same side of 2048
        float2 X0 = (li < NSRC) ? srcb[r0] : tgt[b * NTGT + r0 - NSRC];
        float2 X1 = (li < NSRC) ? srcb[r1] : tgt[b * NTGT + r1 - NSRC];
        const ull xp0 = pack2(X0.x, X0.x), yp0 = pack2(X0.y, X0.y);
        const ull xp1 = pack2(X1.x, X1.x), yp1 = pack2(X1.y, X1.y);
        float c0 = c2 * (X0.x * X0.x + X0.y * X0.y);
        float c1 = c2 * (X1.x * X1.x + X1.y * X1.y);
        const ull cr0 = pack2(c0, c0), cr1 = pack2(c1, c1);

        ull ax0 = 0ull, ay0 = 0ull, ax1 = 0ull, ay1 = 0ull;
        const int qb = w * 64;
        #pragma unroll 4
        for (int t = 0; t < 64; t++) {
            ulonglong2 UV = *(const ulonglong2*)&sUV[qb + t];
            ulonglong2 AP = *(const ulonglong2*)&sAP[qb + t];
            ull PY = *(const ull*)&sPY[qb + t];
            rbf_row(UV.x, UV.y, AP.x, AP.y, PY, xp0, yp0, cr0, ax0, ay0);
            rbf_row(UV.x, UV.y, AP.x, AP.y, PY, xp1, yp1, cr1, ax1, ay1);
        }
        __syncthreads();                      // table reads done; red aliases sUV
        red[0][w * 32 + lane] = ax0;
        red[1][w * 32 + lane] = ay0;
        red[2][w * 32 + lane] = ax1;
        red[3][w * 32 + lane] = ay1;
        __syncthreads();

        if (w == 0) {
            ull s0 = red[0][lane], s1 = red[1][lane];
            ull s2 = red[2][lane], s3 = red[3][lane];
            #pragma unroll
            for (int ww = 1; ww < 8; ww++) {
                s0 = add2(s0, red[0][ww * 32 + lane]);
                s1 = add2(s1, red[1][ww * 32 + lane]);
                s2 = add2(s2, red[2][ww * 32 + lane]);
                s3 = add2(s3, red[3][ww * 32 + lane]);
            }
            float e0, e1, f0, f1;
            unpack2(s0, e0, e1); unpack2(s1, f0, f1);
            g_p1[sj][i0 + lane] = make_float2(e0 + e1, f0 + f1);
            unpack2(s2, e0, e1); unpack2(s3, f0, f1);
            g_p1[sj][i0 + 32 + lane] = make_float2(e0 + e1, f0 + f1);
        }
    }

    // ======================= Grid barrier =======================
    __threadfence();
    __syncthreads();
    if (tid == 0) {
        ull old = atomicAdd(&g_ctr, 1ull);
        ull target = (old & ~(ull)(NCTA - 1)) + (ull)NCTA;
        while (*(volatile ull*)&g_ctr < target) __nanosleep(64);
        __threadfence();
    }
    __syncthreads();

    // ======================= Phase B: dp2 + output =======================
    {
        const int grp = g >> 2;              // 0..127: 64-row target group
        const int sj  = g & 3;               // j-quarter
        const int t0  = grp * 64;            // global target row base
        const int b   = t0 >> 11;

        // Stage 256 pairs, rebuilding shape1 pack from dp1 partials.
        {
            const int q = tid;               // 256 threads, 256 entries
            const int p = sj * 256 + q;      // pair within batch
            const int j0 = 2 * p, j1 = 2 * p + 1;
            const int l0 = b * NLAND + j0, l1 = b * NLAND + j1;
            float2 pa0 = g_p1[0][l0], pb0 = g_p1[1][l0];
            float2 pa1 = g_p1[0][l1], pb1 = g_p1[1][l1];
            float2 s0 = src[b * NSRC + j0], s1 = src[b * NSRC + j1];
            float2 q0 = mom[b * NSRC + j0], q1 = mom[b * NSRC + j1];
            float s0x = fmaf(TAUF, pa0.x + pb0.x, s0.x);
            float s0y = fmaf(TAUF, pa0.y + pb0.y, s0.y);
            float s1x = fmaf(TAUF, pa1.x + pb1.x, s1.x);
            float s1y = fmaf(TAUF, pa1.y + pb1.y, s1.y);
            sUV[q] = make_float4(m2 * s0x, m2 * s1x, m2 * s0y, m2 * s1y);
            sAP[q] = make_float4(c2 * (s0x * s0x + s0y * s0y),
                                 c2 * (s1x * s1x + s1y * s1y), q0.x, q1.x);
            sPY[q] = make_float2(q0.y, q1.y);
        }
        __syncthreads();

        // This lane's two target rows, advected to shape1.
        const int ta = t0 + lane, tb2 = ta + 32;
        const int rta = ta & (NTGT - 1), rtb = tb2 & (NTGT - 1);
        const int la = b * NLAND + NSRC + rta, lb = b * NLAND + NSRC + rtb;
        float2 Ta = tgt[ta], Tb = tgt[tb2];
        float2 da0 = g_p1[0][la], da1 = g_p1[1][la];
        float2 db0 = g_p1[0][lb], db1 = g_p1[1][lb];
        float2 X0 = make_float2(fmaf(TAUF, da0.x + da1.x, Ta.x),
                                fmaf(TAUF, da0.y + da1.y, Ta.y));
        float2 X1 = make_float2(fmaf(TAUF, db0.x + db1.x, Tb.x),
                                fmaf(TAUF, db0.y + db1.y, Tb.y));
        const ull xp0 = pack2(X0.x, X0.x), yp0 = pack2(X0.y, X0.y);
        const ull xp1 = pack2(X1.x, X1.x), yp1 = pack2(X1.y, X1.y);
        float c0 = c2 * (X0.x * X0.x + X0.y * X0.y);
        float c1 = c2 * (X1.x * X1.x + X1.y * X1.y);
        const ull cr0 = pack2(c0, c0), cr1 = pack2(c1, c1);

        ull ax0 = 0ull, ay0 = 0ull, ax1 = 0ull, ay1 = 0ull;
        const int qb = w * 32;
        #pragma unroll 4
        for (int t = 0; t < 32; t++) {
            ulonglong2 UV = *(const ulonglong2*)&sUV[qb + t];
            ulonglong2 AP = *(const ulonglong2*)&sAP[qb + t];
            ull PY = *(const ull*)&sPY[qb + t];
            rbf_row(UV.x, UV.y, AP.x, AP.y, PY, xp0, yp0, cr0, ax0, ay0);
            rbf_row(UV.x, UV.y, AP.x, AP.y, PY, xp1, yp1, cr1, ax1, ay1);
        }
        __syncthreads();                      // table reads done; red aliases sUV
        red[0][w * 32 + lane] = ax0;
        red[1][w * 32 + lane] = ay0;
        red[2][w * 32 + lane] = ax1;
        red[3][w * 32 + lane] = ay1;
        __syncthreads();

        if (w == 0) {
            ull s0 = red[0][lane], s1 = red[1][lane];
            ull s2 = red[2][lane], s3 = red[3][lane];
            #pragma unroll
            for (int ww = 1; ww < 8; ww++) {
                s0 = add2(s0, red[0][ww * 32 + lane]);
                s1 = add2(s1, red[1][ww * 32 + lane]);
                s2 = add2(s2, red[2][ww * 32 + lane]);
                s3 = add2(s3, red[3][ww * 32 + lane]);
            }
            float e0, e1, f0, f1;
            unpack2(s0, e0, e1); unpack2(s1, f0, f1);
            g_p2[sj][ta] = make_float2(e0 + e1, f0 + f1);
            unpack2(s2, e0, e1); unpack2(s3, f0, f1);
            g_p2[sj][tb2] = make_float2(e0 + e1, f0 + f1);

            __threadfence();                  // release partials
            __syncwarp();
            unsigned old = 0;
            if (lane == 0) old = atomicAdd(&g_flag[grp], 1u);
            old = __shfl_sync(0xffffffffu, old, 0);
            if ((old & 3u) == 3u) {           // 4th arrival: combine + writeout
                __threadfence();              // acquire peer partials
                float2 p0 = __ldcg(&g_p2[0][ta]);
                float2 p1 = __ldcg(&g_p2[1][ta]);
                float2 p2 = __ldcg(&g_p2[2][ta]);
                float2 p3 = __ldcg(&g_p2[3][ta]);
                out[ta] = make_float2(
                    fmaf(TAUF, (p0.x + p1.x) + (p2.x + p3.x), X0.x),
                    fmaf(TAUF, (p0.y + p1.y) + (p2.y + p3.y), X0.y));
                p0 = __ldcg(&g_p2[0][tb2]);
                p1 = __ldcg(&g_p2[1][tb2]);
                p2 = __ldcg(&g_p2[2][tb2]);
                p3 = __ldcg(&g_p2[3][tb2]);
                out[tb2] = make_float2(
                    fmaf(TAUF, (p0.x + p1.x) + (p2.x + p3.x), X1.x),
                    fmaf(TAUF, (p0.y + p1.y) + (p2.y + p3.y), X1.y));
            }
        }
    }
}

// ---------------------------------------------------------------------------
extern "C" void kernel_launch(void* const* d_in, const int* in_sizes, int n_in,
                              void* d_out, int out_size)
{
    const float2* mom = (const float2*)d_in[0];
    const float2* src = (const float2*)d_in[1];
    const float2* tgt = (const float2*)d_in[2];
    const float*  sig = (const float*)d_in[3];
    float2* out = (float2*)d_out;

    fused_kernel<<<NCTA, 256>>>(mom, src, tgt, sig, out);
}